// round 12
// baseline (speedup 1.0000x reference)
#include <cuda_runtime.h>
#include <math.h>

// ---------------------------------------------------------------------------
// fs_net_loss — single fused kernel, converged streaming (~93% HBM spec).
// (R11 __ldcs experiment falsified and reverted: default caching is fastest.)
// Phase 1: 592 blocks x 256 thr, exactly 5 fully-unrolled 4-pair batches +
//   one predicated residual load (trip counts compile-time for NBLK=592).
//   Batch 0 peeled; small rot1/rot2/tran/size losses computed in every block
//   under batch-0 memory latency. Recon partial -> 2^-24 fixed-point u64
//   atomic (exactly commutative => deterministic).
// Phase 2: last block (atomic counter): shuffle-reduce register-resident
//   smalls + one u64 read, write out[5], reset accumulators.
// ---------------------------------------------------------------------------

#define BS 128
#define N_PTS 32768
#define RECON_ELEMS (BS * N_PTS * 3)          // 12,582,912
#define RECON_V4   (RECON_ELEMS / 4)          // 3,145,728
#define NBLK 592                               // 148 SMs x 4 blocks -> one wave
#define NTHR 256
#define NWARP (NTHR / 32)
#define STRIDE (NBLK * NTHR)                   // 151,552
#define NBATCH 5                               // 5 x 4 x STRIDE = 3,031,040
#define RESID_LIMIT (RECON_V4 - NBATCH * 4 * STRIDE)  // 114,688
#define BASE 12
#define FX_SCALE 16777216.0f                   // 2^24
#define FX_INV   (1.0 / 16777216.0)

__device__ unsigned long long g_recon_fx = 0ull;
__device__ unsigned int       g_counter  = 0u;

__device__ __constant__ float c_cos[BASE] = {
    1.0f,  0.8660254037844387f,  0.5f,  0.0f, -0.5f, -0.8660254037844387f,
   -1.0f, -0.8660254037844387f, -0.5f,  0.0f,  0.5f,  0.8660254037844387f };
__device__ __constant__ float c_sin[BASE] = {
    0.0f,  0.5f,  0.8660254037844387f,  1.0f,  0.8660254037844387f,  0.5f,
    0.0f, -0.5f, -0.8660254037844387f, -1.0f, -0.8660254037844387f, -0.5f };

__device__ __forceinline__ float l1v4(const float4 x, const float4 y) {
    return fabsf(x.x - y.x) + fabsf(x.y - y.y) +
           fabsf(x.z - y.z) + fabsf(x.w - y.w);
}

__device__ __forceinline__ float warp_sum(float v) {
    #pragma unroll
    for (int off = 16; off > 0; off >>= 1)
        v += __shfl_down_sync(0xffffffffu, v, off);
    return v;
}

__global__ __launch_bounds__(NTHR, 4) void fsnet_fused_kernel(
    const float4* __restrict__ a,    // pred_Recon as float4
    const float4* __restrict__ bb,   // gt_Recon as float4
    const float* __restrict__ pR1,   // [BS,3]
    const float* __restrict__ pR2,   // [BS,3]
    const float* __restrict__ pT,    // [BS,3]
    const float* __restrict__ pS,    // [BS,3]
    const float* __restrict__ gR,    // [BS,3,3]
    const float* __restrict__ gT,    // [BS,3]
    const float* __restrict__ gS,    // [BS,3]
    const int*   __restrict__ sym,   // [BS,6]
    float* __restrict__ out)         // [5]
{
    const int tid  = threadIdx.x;
    const int lane = tid & 31;
    const int wid  = tid >> 5;

    // ---- peel batch 0: issue 8 streaming loads, then hide small-loss work ----
    const int i0 = blockIdx.x * NTHR + tid;      // in [0, STRIDE)
    const float4 xa0 = a[i0];
    const float4 xb0 = bb[i0];
    const float4 xa1 = a[i0 + STRIDE];
    const float4 xb1 = bb[i0 + STRIDE];
    const float4 xa2 = a[i0 + 2 * STRIDE];
    const float4 xb2 = bb[i0 + 2 * STRIDE];
    const float4 xa3 = a[i0 + 3 * STRIDE];
    const float4 xb3 = bb[i0 + 3 * STRIDE];

    // ---- small losses (every block, hidden under batch-0 latency) ----
    float rot1 = 0.0f, rot2m = 0.0f, maskf = 0.0f, tr = 0.0f, sz = 0.0f;
    if (tid < BS) {
        const int b = tid;
        const float* R = gR + b * 9;
        const float r00 = R[0], r01 = R[1], r02 = R[2];
        const float r10 = R[3], r11 = R[4], r12 = R[5];
        const float r20 = R[6], r21 = R[7], r22 = R[8];

        // rot1: +/- column 1 of R
        const float p0 = pR1[b*3+0], p1 = pR1[b*3+1], p2 = pR1[b*3+2];
        const float l1a = (fabsf(p0 - r01) + fabsf(p1 - r11) + fabsf(p2 - r21)) * (1.0f/3.0f);
        const float l1b = (fabsf(p0 + r01) + fabsf(p1 + r11) + fabsf(p2 + r21)) * (1.0f/3.0f);
        rot1 = (sym[b*6+2] == 1) ? fminf(l1a, l1b) : l1a;

        // rot2: cos(th_k)*col0(R) - sin(th_k)*col2(R), k = 0..11
        const float q0 = pR2[b*3+0], q1 = pR2[b*3+1], q2 = pR2[b*3+2];
        float best = 3.402823466e38f;
        #pragma unroll
        for (int k = 0; k < BASE; k++) {
            const float ck = c_cos[k], sk = c_sin[k];
            const float w0 = ck * r00 - sk * r02;
            const float w1 = ck * r10 - sk * r12;
            const float w2 = ck * r20 - sk * r22;
            const float l = (fabsf(q0 - w0) + fabsf(q1 - w1) + fabsf(q2 - w2)) * (1.0f/3.0f);
            best = fminf(best, l);
        }
        maskf = (sym[b*6+0] == 0) ? 1.0f : 0.0f;
        rot2m = best * maskf;

        tr = fabsf(pT[b*3+0] - gT[b*3+0]) +
             fabsf(pT[b*3+1] - gT[b*3+1]) +
             fabsf(pT[b*3+2] - gT[b*3+2]);
        sz = fabsf(pS[b*3+0] - gS[b*3+0]) +
             fabsf(pS[b*3+1] - gS[b*3+1]) +
             fabsf(pS[b*3+2] - gS[b*3+2]);
    }

    // ---- consume batch 0, then exactly NBATCH-1 more batches (unrolled) ----
    float s0 = l1v4(xa0, xb0);
    float s1 = l1v4(xa1, xb1);
    float s2 = l1v4(xa2, xb2);
    float s3 = l1v4(xa3, xb3);
    #pragma unroll
    for (int j = 1; j < NBATCH; j++) {
        const int i = i0 + j * 4 * STRIDE;
        const float4 ya0 = a[i];
        const float4 yb0 = bb[i];
        const float4 ya1 = a[i + STRIDE];
        const float4 yb1 = bb[i + STRIDE];
        const float4 ya2 = a[i + 2 * STRIDE];
        const float4 yb2 = bb[i + 2 * STRIDE];
        const float4 ya3 = a[i + 3 * STRIDE];
        const float4 yb3 = bb[i + 3 * STRIDE];
        s0 += l1v4(ya0, yb0);
        s1 += l1v4(ya1, yb1);
        s2 += l1v4(ya2, yb2);
        s3 += l1v4(ya3, yb3);
    }
    // predicated residual: only threads with i0 < RESID_LIMIT have one more
    if (i0 < RESID_LIMIT)
        s0 += l1v4(a[i0 + NBATCH * 4 * STRIDE], bb[i0 + NBATCH * 4 * STRIDE]);
    float s = warp_sum((s0 + s1) + (s2 + s3));

    __shared__ float warp_s[NWARP];
    if (lane == 0) warp_s[wid] = s;
    __syncthreads();
    __shared__ bool is_last;
    if (tid == 0) {
        float bsum = 0.0f;
        #pragma unroll
        for (int w = 0; w < NWARP; w++) bsum += warp_s[w];
        const long long fx = __float2ll_rn(bsum * FX_SCALE);
        atomicAdd(&g_recon_fx, (unsigned long long)fx);
        __threadfence();
        unsigned int v = atomicAdd(&g_counter, 1u);
        is_last = (v == (unsigned int)(NBLK - 1));
    }
    __syncthreads();
    if (!is_last) return;

    // ---- Phase 2: pure register-resident tail ----
    const float w_rot1 = warp_sum(rot1);
    const float w_rot2 = warp_sum(rot2m);
    const float w_mask = warp_sum(maskf);
    const float w_tr   = warp_sum(tr);
    const float w_sz   = warp_sum(sz);
    __shared__ float small_ws[NWARP][5];
    if (lane == 0) {
        small_ws[wid][0] = w_rot1;
        small_ws[wid][1] = w_rot2;
        small_ws[wid][2] = w_mask;
        small_ws[wid][3] = w_tr;
        small_ws[wid][4] = w_sz;
    }
    __syncthreads();

    if (tid == 0) {
        const float recon_total = (float)((double)g_recon_fx * FX_INV);
        float t_rot1 = 0.0f, t_rot2 = 0.0f, t_mask = 0.0f, t_tr = 0.0f, t_sz = 0.0f;
        #pragma unroll
        for (int w = 0; w < NWARP; w++) {   // warps 4..7 hold zeros
            t_rot1 += small_ws[w][0];
            t_rot2 += small_ws[w][1];
            t_mask += small_ws[w][2];
            t_tr   += small_ws[w][3];
            t_sz   += small_ws[w][4];
        }
        out[0] = 8.0f * t_rot1 * (1.0f / (float)BS);
        out[1] = 8.0f * ((t_mask > 0.0f) ? t_rot2 / fmaxf(t_mask, 1.0f) : 0.0f);
        out[2] = 8.0f * recon_total * (1.0f / (float)RECON_ELEMS);
        out[3] = 8.0f * t_tr * (1.0f / (float)(BS * 3));
        out[4] = 8.0f * t_sz * (1.0f / (float)(BS * 3));
        g_recon_fx = 0ull;   // reset for next graph replay
        g_counter  = 0u;
    }
}

extern "C" void kernel_launch(void* const* d_in, const int* in_sizes, int n_in,
                              void* d_out, int out_size)
{
    const float* pR1  = (const float*)d_in[0];
    const float* pR2  = (const float*)d_in[1];
    const float* pRec = (const float*)d_in[2];
    const float* pT   = (const float*)d_in[3];
    const float* pS   = (const float*)d_in[4];
    const float* gR   = (const float*)d_in[5];
    const float* gRec = (const float*)d_in[6];
    const float* gT   = (const float*)d_in[7];
    const float* gS   = (const float*)d_in[8];
    const int*   sym  = (const int*)d_in[9];
    float* out = (float*)d_out;

    fsnet_fused_kernel<<<NBLK, NTHR>>>((const float4*)pRec, (const float4*)gRec,
                                       pR1, pR2, pT, pS, gR, gT, gS, sym, out);
}

// round 13
// speedup vs baseline: 1.0378x; 1.0378x over previous
#include <cuda_runtime.h>
#include <math.h>

// ---------------------------------------------------------------------------
// fs_net_loss — single fused kernel, converged streaming (~93% HBM spec).
// CANONICAL BEST (R10 form, 14.496us measured): dynamic 4-pair streaming loop.
//   R11 (__ldcs) and R12 (static unroll) both measured 14.944 -> reverted.
// Phase 1: 592 blocks x 256 thr, 4-pair batched float4 streaming (MLP=8).
//   Batch 0 peeled; the tiny rot1/rot2/tran/size losses are computed in
//   EVERY block while batch-0 loads are in flight (hidden under mem latency),
//   collapsing to 5 registers. Recon partial -> 2^-24 fixed-point u64 atomic
//   (exactly commutative => deterministic).
// Phase 2: last block (atomic counter) shuffle-reduces the 5 register-resident
//   smalls + reads one u64, writes out[5], resets accumulators.
// ---------------------------------------------------------------------------

#define BS 128
#define N_PTS 32768
#define RECON_ELEMS (BS * N_PTS * 3)          // 12,582,912
#define RECON_V4   (RECON_ELEMS / 4)          // 3,145,728
#define NBLK 592                               // 148 SMs x 4 blocks -> one wave
#define NTHR 256
#define NWARP (NTHR / 32)
#define STRIDE (NBLK * NTHR)                   // 151,552
#define BASE 12
#define FX_SCALE 16777216.0f                   // 2^24
#define FX_INV   (1.0 / 16777216.0)

__device__ unsigned long long g_recon_fx = 0ull;
__device__ unsigned int       g_counter  = 0u;

__device__ __constant__ float c_cos[BASE] = {
    1.0f,  0.8660254037844387f,  0.5f,  0.0f, -0.5f, -0.8660254037844387f,
   -1.0f, -0.8660254037844387f, -0.5f,  0.0f,  0.5f,  0.8660254037844387f };
__device__ __constant__ float c_sin[BASE] = {
    0.0f,  0.5f,  0.8660254037844387f,  1.0f,  0.8660254037844387f,  0.5f,
    0.0f, -0.5f, -0.8660254037844387f, -1.0f, -0.8660254037844387f, -0.5f };

__device__ __forceinline__ float l1v4(const float4 x, const float4 y) {
    return fabsf(x.x - y.x) + fabsf(x.y - y.y) +
           fabsf(x.z - y.z) + fabsf(x.w - y.w);
}

__device__ __forceinline__ float warp_sum(float v) {
    #pragma unroll
    for (int off = 16; off > 0; off >>= 1)
        v += __shfl_down_sync(0xffffffffu, v, off);
    return v;
}

__global__ __launch_bounds__(NTHR, 4) void fsnet_fused_kernel(
    const float4* __restrict__ a,    // pred_Recon as float4
    const float4* __restrict__ bb,   // gt_Recon as float4
    const float* __restrict__ pR1,   // [BS,3]
    const float* __restrict__ pR2,   // [BS,3]
    const float* __restrict__ pT,    // [BS,3]
    const float* __restrict__ pS,    // [BS,3]
    const float* __restrict__ gR,    // [BS,3,3]
    const float* __restrict__ gT,    // [BS,3]
    const float* __restrict__ gS,    // [BS,3]
    const int*   __restrict__ sym,   // [BS,6]
    float* __restrict__ out)         // [5]
{
    const int tid  = threadIdx.x;
    const int lane = tid & 31;
    const int wid  = tid >> 5;

    // ---- peel batch 0: issue 8 streaming loads, then hide small-loss work ----
    int i = blockIdx.x * NTHR + tid;             // first batch always in range
    const float4 xa0 = a[i];
    const float4 xb0 = bb[i];
    const float4 xa1 = a[i + STRIDE];
    const float4 xb1 = bb[i + STRIDE];
    const float4 xa2 = a[i + 2 * STRIDE];
    const float4 xb2 = bb[i + 2 * STRIDE];
    const float4 xa3 = a[i + 3 * STRIDE];
    const float4 xb3 = bb[i + 3 * STRIDE];

    // ---- small losses (every block, hidden under batch-0 latency) ----
    float rot1 = 0.0f, rot2m = 0.0f, maskf = 0.0f, tr = 0.0f, sz = 0.0f;
    if (tid < BS) {
        const int b = tid;
        const float* R = gR + b * 9;
        const float r00 = R[0], r01 = R[1], r02 = R[2];
        const float r10 = R[3], r11 = R[4], r12 = R[5];
        const float r20 = R[6], r21 = R[7], r22 = R[8];

        // rot1: +/- column 1 of R
        const float p0 = pR1[b*3+0], p1 = pR1[b*3+1], p2 = pR1[b*3+2];
        const float l1a = (fabsf(p0 - r01) + fabsf(p1 - r11) + fabsf(p2 - r21)) * (1.0f/3.0f);
        const float l1b = (fabsf(p0 + r01) + fabsf(p1 + r11) + fabsf(p2 + r21)) * (1.0f/3.0f);
        rot1 = (sym[b*6+2] == 1) ? fminf(l1a, l1b) : l1a;

        // rot2: cos(th_k)*col0(R) - sin(th_k)*col2(R), k = 0..11
        const float q0 = pR2[b*3+0], q1 = pR2[b*3+1], q2 = pR2[b*3+2];
        float best = 3.402823466e38f;
        #pragma unroll
        for (int k = 0; k < BASE; k++) {
            const float ck = c_cos[k], sk = c_sin[k];
            const float w0 = ck * r00 - sk * r02;
            const float w1 = ck * r10 - sk * r12;
            const float w2 = ck * r20 - sk * r22;
            const float l = (fabsf(q0 - w0) + fabsf(q1 - w1) + fabsf(q2 - w2)) * (1.0f/3.0f);
            best = fminf(best, l);
        }
        maskf = (sym[b*6+0] == 0) ? 1.0f : 0.0f;
        rot2m = best * maskf;

        tr = fabsf(pT[b*3+0] - gT[b*3+0]) +
             fabsf(pT[b*3+1] - gT[b*3+1]) +
             fabsf(pT[b*3+2] - gT[b*3+2]);
        sz = fabsf(pS[b*3+0] - gS[b*3+0]) +
             fabsf(pS[b*3+1] - gS[b*3+1]) +
             fabsf(pS[b*3+2] - gS[b*3+2]);
    }

    // ---- consume batch 0, then stream the rest ----
    float s0 = l1v4(xa0, xb0);
    float s1 = l1v4(xa1, xb1);
    float s2 = l1v4(xa2, xb2);
    float s3 = l1v4(xa3, xb3);
    i += 4 * STRIDE;
    for (; i + 3 * STRIDE < RECON_V4; i += 4 * STRIDE) {
        const float4 ya0 = a[i];
        const float4 yb0 = bb[i];
        const float4 ya1 = a[i + STRIDE];
        const float4 yb1 = bb[i + STRIDE];
        const float4 ya2 = a[i + 2 * STRIDE];
        const float4 yb2 = bb[i + 2 * STRIDE];
        const float4 ya3 = a[i + 3 * STRIDE];
        const float4 yb3 = bb[i + 3 * STRIDE];
        s0 += l1v4(ya0, yb0);
        s1 += l1v4(ya1, yb1);
        s2 += l1v4(ya2, yb2);
        s3 += l1v4(ya3, yb3);
    }
    for (; i < RECON_V4; i += STRIDE)
        s0 += l1v4(a[i], bb[i]);
    float s = warp_sum((s0 + s1) + (s2 + s3));

    __shared__ float warp_s[NWARP];
    if (lane == 0) warp_s[wid] = s;
    __syncthreads();
    __shared__ bool is_last;
    if (tid == 0) {
        float bsum = 0.0f;
        #pragma unroll
        for (int w = 0; w < NWARP; w++) bsum += warp_s[w];
        const long long fx = __float2ll_rn(bsum * FX_SCALE);
        atomicAdd(&g_recon_fx, (unsigned long long)fx);
        __threadfence();
        unsigned int v = atomicAdd(&g_counter, 1u);
        is_last = (v == (unsigned int)(NBLK - 1));
    }
    __syncthreads();
    if (!is_last) return;

    // ---- Phase 2: pure register-resident tail ----
    const float w_rot1 = warp_sum(rot1);
    const float w_rot2 = warp_sum(rot2m);
    const float w_mask = warp_sum(maskf);
    const float w_tr   = warp_sum(tr);
    const float w_sz   = warp_sum(sz);
    __shared__ float small_ws[NWARP][5];
    if (lane == 0) {
        small_ws[wid][0] = w_rot1;
        small_ws[wid][1] = w_rot2;
        small_ws[wid][2] = w_mask;
        small_ws[wid][3] = w_tr;
        small_ws[wid][4] = w_sz;
    }
    __syncthreads();

    if (tid == 0) {
        const float recon_total = (float)((double)g_recon_fx * FX_INV);
        float t_rot1 = 0.0f, t_rot2 = 0.0f, t_mask = 0.0f, t_tr = 0.0f, t_sz = 0.0f;
        #pragma unroll
        for (int w = 0; w < NWARP; w++) {   // warps 4..7 hold zeros
            t_rot1 += small_ws[w][0];
            t_rot2 += small_ws[w][1];
            t_mask += small_ws[w][2];
            t_tr   += small_ws[w][3];
            t_sz   += small_ws[w][4];
        }
        out[0] = 8.0f * t_rot1 * (1.0f / (float)BS);
        out[1] = 8.0f * ((t_mask > 0.0f) ? t_rot2 / fmaxf(t_mask, 1.0f) : 0.0f);
        out[2] = 8.0f * recon_total * (1.0f / (float)RECON_ELEMS);
        out[3] = 8.0f * t_tr * (1.0f / (float)(BS * 3));
        out[4] = 8.0f * t_sz * (1.0f / (float)(BS * 3));
        g_recon_fx = 0ull;   // reset for next graph replay
        g_counter  = 0u;
    }
}

extern "C" void kernel_launch(void* const* d_in, const int* in_sizes, int n_in,
                              void* d_out, int out_size)
{
    const float* pR1  = (const float*)d_in[0];
    const float* pR2  = (const float*)d_in[1];
    const float* pRec = (const float*)d_in[2];
    const float* pT   = (const float*)d_in[3];
    const float* pS   = (const float*)d_in[4];
    const float* gR   = (const float*)d_in[5];
    const float* gRec = (const float*)d_in[6];
    const float* gT   = (const float*)d_in[7];
    const float* gS   = (const float*)d_in[8];
    const int*   sym  = (const int*)d_in[9];
    float* out = (float*)d_out;

    fsnet_fused_kernel<<<NBLK, NTHR>>>((const float4*)pRec, (const float4*)gRec,
                                       pR1, pR2, pT, pS, gR, gT, gS, sym, out);
}